// round 15
// baseline (speedup 1.0000x reference)
#include <cuda_runtime.h>
#include <cuda_bf16.h>
#include <math.h>
#include <stdint.h>

// Problem constants
#define BSZ 2
#define SEQ 2048
#define HID 4096
#define NH  32
#define NKV 8
#define HD  128
#define ROWS (BSZ*SEQ)           // 4096
#define KVD (NKV*HD)             // 1024
#define KVSTR 2048               // packed K|V row stride

// ---------------- scratch ----------------
__device__ float g_Q[(size_t)ROWS * HID];
__device__ float g_KV[(size_t)ROWS * KVSTR];
__device__ float g_O[(size_t)ROWS * HID];
__device__ float g_Xt[(size_t)ROWS * HID];
__device__ float g_Wqt[(size_t)HID * HID];
__device__ float g_Wkvt[(size_t)HID * KVSTR];
__device__ float g_Wot[(size_t)HID * HID];

__device__ __forceinline__ uint32_t smem_u32(const void* p) {
    uint32_t a;
    asm("{ .reg .u64 t; cvta.to.shared.u64 t, %1; cvt.u32.u64 %0, t; }" : "=r"(a) : "l"(p));
    return a;
}
__device__ __forceinline__ void cp16(uint32_t smem_addr, const void* gptr) {
    asm volatile("cp.async.cg.shared.global [%0], [%1], 16;" :: "r"(smem_addr), "l"(gptr) : "memory");
}
#define CP_COMMIT() asm volatile("cp.async.commit_group;" ::: "memory")
#define CP_WAIT(n)  asm volatile("cp.async.wait_group %0;" :: "n"(n) : "memory")

__device__ __forceinline__ uint32_t f2tf32(float f) {
    uint32_t u;
    asm("cvt.rna.tf32.f32 %0, %1;" : "=r"(u) : "f"(f));
    return u;
}
__device__ __forceinline__ float4 round4(float4 v) {
    return make_float4(__uint_as_float(f2tf32(v.x)), __uint_as_float(f2tf32(v.y)),
                       __uint_as_float(f2tf32(v.z)), __uint_as_float(f2tf32(v.w)));
}
__device__ __forceinline__ void mma_tf32(float* c, uint32_t a0, uint32_t a1, uint32_t a2,
                                         uint32_t a3, uint32_t b0, uint32_t b1) {
    asm volatile(
        "mma.sync.aligned.m16n8k8.row.col.f32.tf32.tf32.f32 "
        "{%0,%1,%2,%3}, {%4,%5,%6,%7}, {%8,%9}, {%0,%1,%2,%3};"
        : "+f"(c[0]), "+f"(c[1]), "+f"(c[2]), "+f"(c[3])
        : "r"(a0), "r"(a1), "r"(a2), "r"(a3), "r"(b0), "r"(b1));
}

// ---------------- fused tf32 rounding: X, Wq, Wk|Wv-pack, Wo in ONE launch ----------------
#define CVT_ALL_BLOCKS 14336
__global__ void cvt_all_kernel(const float4* __restrict__ X, float4* __restrict__ Xt,
                               const float4* __restrict__ Wq, float4* __restrict__ Wqt,
                               const float4* __restrict__ Wk, const float4* __restrict__ Wv,
                               float4* __restrict__ Wkvt,
                               const float4* __restrict__ Wo, float4* __restrict__ Wot) {
    const int b = blockIdx.x;
    const int t = threadIdx.x;
    if (b < 8192 || b >= 10240) {
        const float4* in;
        float4* out;
        size_t base;
        if (b < 4096)      { in = X;  out = Xt;  base = (size_t)b * 1024 + t; }
        else if (b < 8192) { in = Wq; out = Wqt; base = (size_t)(b - 4096) * 1024 + t; }
        else               { in = Wo; out = Wot; base = (size_t)(b - 10240) * 1024 + t; }
        float4 v[4];
#pragma unroll
        for (int u = 0; u < 4; u++) v[u] = in[base + u * 256];
#pragma unroll
        for (int u = 0; u < 4; u++) out[base + u * 256] = round4(v[u]);
    } else {
        const float4* in = (b < 9216) ? Wk : Wv;
        const int off = (b < 9216) ? 0 : 256;
        const size_t base = (size_t)((b - 8192) & 1023) * 1024 + t;
        float4 v[4];
#pragma unroll
        for (int u = 0; u < 4; u++) v[u] = in[base + u * 256];
#pragma unroll
        for (int u = 0; u < 4; u++) {
            size_t i = base + u * 256;
            size_t row = i >> 8;
            size_t col = i & 255;
            Wkvt[row * 512 + off + col] = round4(v[u]);
        }
    }
}

// ================= tf32 mma GEMM core (BK=32, 2-stage, 4 warps x 64x64) =================
#define ASTR 36
#define BSTR 136
#define STG_A (128 * ASTR)
#define STG_B (32 * BSTR)
#define STG_FLOATS (STG_A + STG_B)           // 8960
#define GEMM_SMEM_BYTES (2 * STG_FLOATS * 4) // 71680

__device__ __forceinline__ void gemm_body(const float* __restrict__ Ap,
                                          const float* __restrict__ Bp,
                                          float* __restrict__ C,
                                          size_t bm, size_t bn,
                                          int N, int K, int roundFrom,
                                          float* smg, uint32_t smb) {
    const int tid = threadIdx.x;
    const int wid = tid >> 5;
    const int lid = tid & 31;
    const int gi = lid >> 2;
    const int qi = lid & 3;
    const int wm = (wid & 1) * 64;
    const int wn = (wid >> 1) * 64;

    const int aRow = tid >> 3;
    const int aCol = (tid & 7) * 4;
    const int bRow = tid >> 5;
    const int bCol = (tid & 31) * 4;

    float acc[4][8][4];
#pragma unroll
    for (int mt = 0; mt < 4; mt++)
#pragma unroll
        for (int nt = 0; nt < 8; nt++)
#pragma unroll
            for (int r = 0; r < 4; r++) acc[mt][nt][r] = 0.0f;

    auto load_stage = [&](int kstep, int slot) {
        uint32_t as = smb + (uint32_t)(slot * STG_FLOATS) * 4u;
        uint32_t bs = as + STG_A * 4u;
        const int k0 = kstep * 32;
#pragma unroll
        for (int r = 0; r < 8; r++) {
            int row = aRow + r * 16;
            cp16(as + (row * ASTR + aCol) * 4, Ap + (size_t)row * K + k0 + aCol);
        }
#pragma unroll
        for (int r = 0; r < 8; r++) {
            int row = bRow + r * 4;
            cp16(bs + (row * BSTR + bCol) * 4, Bp + (size_t)(k0 + row) * N + bCol);
        }
    };

    const int nsteps = K / 32;
    load_stage(0, 0);
    CP_COMMIT();

    for (int step = 0; step < nsteps; step++) {
        CP_WAIT(0);
        __syncthreads();
        if (step + 1 < nsteps)
            load_stage(step + 1, (step + 1) & 1);
        CP_COMMIT();

        const float* Ab = smg + (step & 1) * STG_FLOATS;
        const float* Bb = Ab + STG_A;
#pragma unroll
        for (int kk = 0; kk < 32; kk += 8) {
            uint32_t a[4][4], b[8][2];
#pragma unroll
            for (int mt = 0; mt < 4; mt++) {
                int r = wm + mt * 16 + gi;
                a[mt][0] = __float_as_uint(Ab[r * ASTR + kk + qi]);
                a[mt][1] = __float_as_uint(Ab[(r + 8) * ASTR + kk + qi]);
                a[mt][2] = __float_as_uint(Ab[r * ASTR + kk + qi + 4]);
                a[mt][3] = __float_as_uint(Ab[(r + 8) * ASTR + kk + qi + 4]);
            }
#pragma unroll
            for (int nt = 0; nt < 8; nt++) {
                int c = wn + nt * 8 + gi;
                b[nt][0] = __float_as_uint(Bb[(kk + qi) * BSTR + c]);
                b[nt][1] = __float_as_uint(Bb[(kk + qi + 4) * BSTR + c]);
            }
#pragma unroll
            for (int mt = 0; mt < 4; mt++)
#pragma unroll
                for (int nt = 0; nt < 8; nt++)
                    mma_tf32(acc[mt][nt], a[mt][0], a[mt][1], a[mt][2], a[mt][3],
                             b[nt][0], b[nt][1]);
        }
    }

#pragma unroll
    for (int mt = 0; mt < 4; mt++) {
#pragma unroll
        for (int nt = 0; nt < 8; nt++) {
            size_t row = bm + wm + mt * 16 + gi;
            size_t col = bn + wn + nt * 8 + qi * 2;
            float v0 = acc[mt][nt][0], v1 = acc[mt][nt][1];
            float v2 = acc[mt][nt][2], v3 = acc[mt][nt][3];
            if ((int)col >= roundFrom) {
                v0 = __uint_as_float(f2tf32(v0));
                v1 = __uint_as_float(f2tf32(v1));
                v2 = __uint_as_float(f2tf32(v2));
                v3 = __uint_as_float(f2tf32(v3));
            }
            *(float2*)&C[row * N + col] = make_float2(v0, v1);
            *(float2*)&C[(row + 8) * N + col] = make_float2(v2, v3);
        }
    }
}

// Merged Q + KV projection
__global__ __launch_bounds__(128)
void tf32_qkv_gemm(const float* __restrict__ A,
                   const float* __restrict__ Wq, const float* __restrict__ Wkv,
                   float* __restrict__ Q, float* __restrict__ KV) {
    extern __shared__ float smg[];
    const uint32_t smb = smem_u32(smg);
    const size_t bm = (size_t)blockIdx.y * 128;
    const size_t bnv = (size_t)blockIdx.x * 128;
    if (bnv < HID) {
        gemm_body(A + bm * HID, Wq + bnv, Q, bm, bnv, HID, HID, HID, smg, smb);
    } else {
        size_t bn = bnv - HID;
        gemm_body(A + bm * HID, Wkv + bn, KV, bm, bn, KVSTR, HID, KVD, smg, smb);
    }
}

__global__ __launch_bounds__(128)
void tf32_mma_gemm(const float* __restrict__ A, const float* __restrict__ B,
                   float* __restrict__ C, int M, int N, int K, int roundFrom) {
    extern __shared__ float smg[];
    const uint32_t smb = smem_u32(smg);
    const size_t bm = (size_t)blockIdx.y * 128;
    const size_t bn = (size_t)blockIdx.x * 128;
    gemm_body(A + bm * K, B + bn, C, bm, bn, N, K, roundFrom, smg, smb);
}

// ---------------- unified RoPE ----------------
#define ROPE_QTOT (ROWS * NH * 64)
#define ROPE_KTOT (ROWS * NKV * 64)
__global__ void rope_all_kernel(float* __restrict__ q, float* __restrict__ kv) {
    int idx = blockIdx.x * blockDim.x + threadIdx.x;
    float* x;
    int nheads, rowstride;
    if (idx < ROPE_QTOT) {
        x = q; nheads = NH; rowstride = HID;
    } else {
        idx -= ROPE_QTOT;
        if (idx >= ROPE_KTOT) return;
        x = kv; nheads = NKV; rowstride = KVSTR;
    }
    int d = idx & 63;
    int h = (idx >> 6) % nheads;
    int row = idx / (64 * nheads);
    int s = row & (SEQ - 1);
    float inv = exp2f(-0.20762050593046938f * (float)d);
    float ang = (float)s * inv;
    float sn, cs;
    sincosf(ang, &sn, &cs);
    size_t base = (size_t)row * rowstride + (size_t)h * HD;
    float x1 = x[base + d];
    float x2 = x[base + d + 64];
    x[base + d]      = __uint_as_float(f2tf32(x1 * cs - x2 * sn));
    x[base + d + 64] = __uint_as_float(f2tf32(x2 * cs + x1 * sn));
}

// ================= Flash attention (tf32 mma, causal, GQA) =================
// BQ=64, BC=32, 128 threads, 2 CTAs/SM. Q fragments held in REGISTERS
// (qa[16][4], loaded once) -> QK inner loop issues only K-LDS + HMMA.
#define QSTR 132
#define KSTR 132
#define VSTR 136
#define SQ_OFF 0
#define SK0_OFF (64 * QSTR)
#define SK1_OFF (SK0_OFF + 32 * KSTR)
#define SV0_OFF (SK1_OFF + 32 * KSTR)
#define SV1_OFF (SV0_OFF + 32 * VSTR)
#define FSM_FLOATS (SV1_OFF + 32 * VSTR)     // 25600
#define FSM_BYTES (FSM_FLOATS * 4)           // 102400

__global__ __launch_bounds__(128)
void flash_mma_kernel(const float* __restrict__ Q, const float* __restrict__ KV,
                      float* __restrict__ O) {
    extern __shared__ float sm[];
    const int tid = threadIdx.x;
    const int wid = tid >> 5;
    const int lid = tid & 31;
    const int gi = lid >> 2;
    const int qi = lid & 3;
    const int wm = wid * 16;

    const int qt = blockIdx.x;
    const int h  = blockIdx.y;
    const int b  = blockIdx.z;
    const int kvh = h >> 2;
    const int q0 = qt * 64;

    const float* Qp = Q + (size_t)b * SEQ * HID + (size_t)h * HD;
    const float* Kp = KV + (size_t)b * SEQ * KVSTR + (size_t)kvh * HD;
    const float* Vp = Kp + KVD;
    float* Op = O + (size_t)b * SEQ * HID + (size_t)h * HD;

    const uint32_t smb = smem_u32(sm);

    // stage Q tile to smem
    for (int i = tid; i < 64 * 32; i += 128) {
        int row = i >> 5, c4 = (i & 31) * 4;
        *(float4*)&sm[SQ_OFF + row * QSTR + c4] =
            *(const float4*)&Qp[(size_t)(q0 + row) * HID + c4];
    }

    // prefetch tile 0 K and V (separate commit groups)
    auto load_k = [&](int j, int slot) {
        uint32_t kb = smb + (slot ? SK1_OFF : SK0_OFF) * 4;
        const size_t r0 = (size_t)j * 32;
        for (int i = tid; i < 32 * 32; i += 128) {
            int row = i >> 5, c4 = (i & 31) * 4;
            cp16(kb + (row * KSTR + c4) * 4, Kp + (r0 + row) * KVSTR + c4);
        }
    };
    auto load_v = [&](int j, int slot) {
        uint32_t vb = smb + (slot ? SV1_OFF : SV0_OFF) * 4;
        const size_t r0 = (size_t)j * 32;
        for (int i = tid; i < 32 * 32; i += 128) {
            int row = i >> 5, c4 = (i & 31) * 4;
            cp16(vb + (row * VSTR + c4) * 4, Vp + (r0 + row) * KVSTR + c4);
        }
    };
    load_k(0, 0);
    CP_COMMIT();
    load_v(0, 0);
    CP_COMMIT();

    // hoist Q fragments into registers (once)
    __syncthreads();
    uint32_t qa[16][4];
#pragma unroll
    for (int kw = 0; kw < 16; kw++) {
        int kk = kw * 8;
        qa[kw][0] = __float_as_uint(sm[SQ_OFF + (wm + gi) * QSTR + kk + qi]);
        qa[kw][1] = __float_as_uint(sm[SQ_OFF + (wm + gi + 8) * QSTR + kk + qi]);
        qa[kw][2] = __float_as_uint(sm[SQ_OFF + (wm + gi) * QSTR + kk + qi + 4]);
        qa[kw][3] = __float_as_uint(sm[SQ_OFF + (wm + gi + 8) * QSTR + kk + qi + 4]);
    }

    float m0 = -1e30f, m1 = -1e30f, l0 = 0.0f, l1 = 0.0f;
    float o[16][4];
#pragma unroll
    for (int f = 0; f < 16; f++)
#pragma unroll
        for (int r = 0; r < 4; r++) o[f][r] = 0.0f;

    const int ntiles = 2 * qt + 2;
    const float qscale = 0.08838834764831845f;

    for (int j = 0; j < ntiles; j++) {
        const int cur = j & 1;
        // pending: [K_j, V_j]; wait all but newest -> K_j done
        CP_WAIT(1);
        __syncthreads();

        if (j + 1 < ntiles) {
            load_k(j + 1, (j + 1) & 1);
        }
        CP_COMMIT();       // pending: [V_j, K_{j+1}]

        const float* sK = sm + (cur ? SK1_OFF : SK0_OFF);
        const float* sV = sm + (cur ? SV1_OFF : SV0_OFF);

        // ---- QK^T (Q from registers) ----
        float s[4][4];
#pragma unroll
        for (int nt = 0; nt < 4; nt++)
#pragma unroll
            for (int r = 0; r < 4; r++) s[nt][r] = 0.0f;

#pragma unroll
        for (int kw = 0; kw < 16; kw++) {
            int kk = kw * 8;
#pragma unroll
            for (int nt = 0; nt < 4; nt++) {
                uint32_t b0 = __float_as_uint(sK[(nt * 8 + gi) * KSTR + kk + qi]);
                uint32_t b1 = __float_as_uint(sK[(nt * 8 + gi) * KSTR + kk + qi + 4]);
                mma_tf32(s[nt], qa[kw][0], qa[kw][1], qa[kw][2], qa[kw][3], b0, b1);
            }
        }

        // ---- softmax ----
        const int row0 = q0 + wm + gi;
        const int row1 = row0 + 8;
        const bool diag = (j >= 2 * qt);
#pragma unroll
        for (int nt = 0; nt < 4; nt++) {
#pragma unroll
            for (int r = 0; r < 4; r++) s[nt][r] *= qscale;
            if (diag) {
                int c = j * 32 + nt * 8 + 2 * qi;
                if (c > row0)     s[nt][0] = -1e30f;
                if (c + 1 > row0) s[nt][1] = -1e30f;
                if (c > row1)     s[nt][2] = -1e30f;
                if (c + 1 > row1) s[nt][3] = -1e30f;
            }
        }
        float mx0 = -1e30f, mx1 = -1e30f;
#pragma unroll
        for (int nt = 0; nt < 4; nt++) {
            mx0 = fmaxf(mx0, fmaxf(s[nt][0], s[nt][1]));
            mx1 = fmaxf(mx1, fmaxf(s[nt][2], s[nt][3]));
        }
        mx0 = fmaxf(mx0, __shfl_xor_sync(0xffffffffu, mx0, 1));
        mx0 = fmaxf(mx0, __shfl_xor_sync(0xffffffffu, mx0, 2));
        mx1 = fmaxf(mx1, __shfl_xor_sync(0xffffffffu, mx1, 1));
        mx1 = fmaxf(mx1, __shfl_xor_sync(0xffffffffu, mx1, 2));

        float mn0 = fmaxf(m0, mx0), mn1 = fmaxf(m1, mx1);
        float sc0 = __expf(m0 - mn0), sc1 = __expf(m1 - mn1);
        m0 = mn0; m1 = mn1;

        float rs0 = 0.0f, rs1 = 0.0f;
        uint32_t pu[4][4];
#pragma unroll
        for (int nt = 0; nt < 4; nt++) {
            float p0 = __expf(s[nt][0] - m0);
            float p1 = __expf(s[nt][1] - m0);
            float p2 = __expf(s[nt][2] - m1);
            float p3 = __expf(s[nt][3] - m1);
            rs0 += p0 + p1;
            rs1 += p2 + p3;
            pu[nt][0] = f2tf32(p0);
            pu[nt][1] = f2tf32(p1);
            pu[nt][2] = f2tf32(p2);
            pu[nt][3] = f2tf32(p3);
        }
        rs0 += __shfl_xor_sync(0xffffffffu, rs0, 1);
        rs0 += __shfl_xor_sync(0xffffffffu, rs0, 2);
        rs1 += __shfl_xor_sync(0xffffffffu, rs1, 1);
        rs1 += __shfl_xor_sync(0xffffffffu, rs1, 2);
        l0 = l0 * sc0 + rs0;
        l1 = l1 * sc1 + rs1;
#pragma unroll
        for (int f = 0; f < 16; f++) {
            o[f][0] *= sc0; o[f][1] *= sc0;
            o[f][2] *= sc1; o[f][3] *= sc1;
        }

        // pending: [V_j, K_{j+1}]; wait all but newest -> V_j done
        CP_WAIT(1);
        __syncthreads();

        if (j + 1 < ntiles) {
            load_v(j + 1, (j + 1) & 1);
        }
        CP_COMMIT();       // pending: [K_{j+1}, V_{j+1}]

        // ---- PV ----
        const int srcA = (gi << 2) + (qi >> 1);
        const int srcB = srcA + 2;
        const bool odd = (qi & 1);
#pragma unroll
        for (int kc = 0; kc < 4; kc++) {
            uint32_t x0 = __shfl_sync(0xffffffffu, pu[kc][0], srcA);
            uint32_t x1 = __shfl_sync(0xffffffffu, pu[kc][1], srcA);
            uint32_t y0 = __shfl_sync(0xffffffffu, pu[kc][0], srcB);
            uint32_t y1 = __shfl_sync(0xffffffffu, pu[kc][1], srcB);
            uint32_t x2 = __shfl_sync(0xffffffffu, pu[kc][2], srcA);
            uint32_t x3 = __shfl_sync(0xffffffffu, pu[kc][3], srcA);
            uint32_t y2 = __shfl_sync(0xffffffffu, pu[kc][2], srcB);
            uint32_t y3 = __shfl_sync(0xffffffffu, pu[kc][3], srcB);
            uint32_t a0 = odd ? x1 : x0;
            uint32_t a2 = odd ? y1 : y0;
            uint32_t a1 = odd ? x3 : x2;
            uint32_t a3 = odd ? y3 : y2;
#pragma unroll
            for (int nt2 = 0; nt2 < 16; nt2++) {
                uint32_t b0 = __float_as_uint(sV[(kc * 8 + qi) * VSTR + nt2 * 8 + gi]);
                uint32_t b1 = __float_as_uint(sV[(kc * 8 + qi + 4) * VSTR + nt2 * 8 + gi]);
                mma_tf32(o[nt2], a0, a1, a2, a3, b0, b1);
            }
        }
    }

    // epilogue
    const float inv0 = 1.0f / l0;
    const float inv1 = 1.0f / l1;
    const size_t r0 = (size_t)(q0 + wm + gi);
    const size_t r1 = r0 + 8;
#pragma unroll
    for (int nt2 = 0; nt2 < 16; nt2++) {
        int col = nt2 * 8 + 2 * qi;
        *(float2*)&Op[r0 * HID + col] = make_float2(
            __uint_as_float(f2tf32(o[nt2][0] * inv0)),
            __uint_as_float(f2tf32(o[nt2][1] * inv0)));
        *(float2*)&Op[r1 * HID + col] = make_float2(
            __uint_as_float(f2tf32(o[nt2][2] * inv1)),
            __uint_as_float(f2tf32(o[nt2][3] * inv1)));
    }
}

// ---------------- launch ----------------
extern "C" void kernel_launch(void* const* d_in, const int* in_sizes, int n_in,
                              void* d_out, int out_size) {
    (void)in_sizes; (void)n_in; (void)out_size;
    const float* X  = (const float*)d_in[0];
    const float* Wq = (const float*)d_in[3];
    const float* Wk = (const float*)d_in[4];
    const float* Wv = (const float*)d_in[5];
    const float* Wo = (const float*)d_in[6];
    float* out = (float*)d_out;

    float *Qb, *KVb, *Ob, *Xt, *Wqt, *Wkvt, *Wot;
    cudaGetSymbolAddress((void**)&Qb, g_Q);
    cudaGetSymbolAddress((void**)&KVb, g_KV);
    cudaGetSymbolAddress((void**)&Ob, g_O);
    cudaGetSymbolAddress((void**)&Xt, g_Xt);
    cudaGetSymbolAddress((void**)&Wqt, g_Wqt);
    cudaGetSymbolAddress((void**)&Wkvt, g_Wkvt);
    cudaGetSymbolAddress((void**)&Wot, g_Wot);

    cudaFuncSetAttribute(flash_mma_kernel, cudaFuncAttributeMaxDynamicSharedMemorySize, FSM_BYTES);
    cudaFuncSetAttribute(tf32_mma_gemm, cudaFuncAttributeMaxDynamicSharedMemorySize, GEMM_SMEM_BYTES);
    cudaFuncSetAttribute(tf32_qkv_gemm, cudaFuncAttributeMaxDynamicSharedMemorySize, GEMM_SMEM_BYTES);

    // launch 0: fused tf32 rounding/packing (X, Wq, Wk|Wv, Wo)
    cvt_all_kernel<<<CVT_ALL_BLOCKS, 256>>>((const float4*)X, (float4*)Xt,
                                            (const float4*)Wq, (float4*)Wqt,
                                            (const float4*)Wk, (const float4*)Wv,
                                            (float4*)Wkvt,
                                            (const float4*)Wo, (float4*)Wot);

    // launch 1: merged Q + KV projection
    tf32_qkv_gemm<<<dim3((HID + KVSTR) / 128, ROWS / 128), 128, GEMM_SMEM_BYTES>>>(
        Xt, Wqt, Wkvt, Qb, KVb);

    // launch 2: unified RoPE
    {
        int tot = ROPE_QTOT + ROPE_KTOT;
        rope_all_kernel<<<(tot + 255) / 256, 256>>>(Qb, KVb);
    }

    // launch 3: flash attention (Q-in-registers)
    flash_mma_kernel<<<dim3(SEQ / 64, NH, BSZ), 128, FSM_BYTES>>>(Qb, KVb, Ob);

    // launch 4: output projection
    tf32_mma_gemm<<<dim3(HID / 128, ROWS / 128), 128, GEMM_SMEM_BYTES>>>(
        Ob, Wot, out, ROWS, HID, HID, HID);
}

// round 16
// speedup vs baseline: 1.0556x; 1.0556x over previous
#include <cuda_runtime.h>
#include <cuda_bf16.h>
#include <math.h>
#include <stdint.h>

// Problem constants
#define BSZ 2
#define SEQ 2048
#define HID 4096
#define NH  32
#define NKV 8
#define HD  128
#define ROWS (BSZ*SEQ)           // 4096
#define KVD (NKV*HD)             // 1024
#define KVSTR 2048               // packed K|V row stride

// ---------------- scratch ----------------
__device__ float g_Q[(size_t)ROWS * HID];
__device__ float g_KV[(size_t)ROWS * KVSTR];
__device__ float g_O[(size_t)ROWS * HID];
__device__ float g_Xt[(size_t)ROWS * HID];
__device__ float g_Wqt[(size_t)HID * HID];
__device__ float g_Wkvt[(size_t)HID * KVSTR];
__device__ float g_Wot[(size_t)HID * HID];

__device__ __forceinline__ uint32_t smem_u32(const void* p) {
    uint32_t a;
    asm("{ .reg .u64 t; cvta.to.shared.u64 t, %1; cvt.u32.u64 %0, t; }" : "=r"(a) : "l"(p));
    return a;
}
__device__ __forceinline__ void cp16(uint32_t smem_addr, const void* gptr) {
    asm volatile("cp.async.cg.shared.global [%0], [%1], 16;" :: "r"(smem_addr), "l"(gptr) : "memory");
}
#define CP_COMMIT() asm volatile("cp.async.commit_group;" ::: "memory")
#define CP_WAIT(n)  asm volatile("cp.async.wait_group %0;" :: "n"(n) : "memory")

__device__ __forceinline__ uint32_t f2tf32(float f) {
    uint32_t u;
    asm("cvt.rna.tf32.f32 %0, %1;" : "=r"(u) : "f"(f));
    return u;
}
__device__ __forceinline__ float4 round4(float4 v) {
    return make_float4(__uint_as_float(f2tf32(v.x)), __uint_as_float(f2tf32(v.y)),
                       __uint_as_float(f2tf32(v.z)), __uint_as_float(f2tf32(v.w)));
}
__device__ __forceinline__ void mma_tf32(float* c, uint32_t a0, uint32_t a1, uint32_t a2,
                                         uint32_t a3, uint32_t b0, uint32_t b1) {
    asm volatile(
        "mma.sync.aligned.m16n8k8.row.col.f32.tf32.tf32.f32 "
        "{%0,%1,%2,%3}, {%4,%5,%6,%7}, {%8,%9}, {%0,%1,%2,%3};"
        : "+f"(c[0]), "+f"(c[1]), "+f"(c[2]), "+f"(c[3])
        : "r"(a0), "r"(a1), "r"(a2), "r"(a3), "r"(b0), "r"(b1));
}

// ---------------- fused tf32 rounding: X, Wq, Wk|Wv-pack, Wo in ONE launch ----------------
#define CVT_ALL_BLOCKS 14336
__global__ void cvt_all_kernel(const float4* __restrict__ X, float4* __restrict__ Xt,
                               const float4* __restrict__ Wq, float4* __restrict__ Wqt,
                               const float4* __restrict__ Wk, const float4* __restrict__ Wv,
                               float4* __restrict__ Wkvt,
                               const float4* __restrict__ Wo, float4* __restrict__ Wot) {
    const int b = blockIdx.x;
    const int t = threadIdx.x;
    if (b < 8192 || b >= 10240) {
        const float4* in;
        float4* out;
        size_t base;
        if (b < 4096)      { in = X;  out = Xt;  base = (size_t)b * 1024 + t; }
        else if (b < 8192) { in = Wq; out = Wqt; base = (size_t)(b - 4096) * 1024 + t; }
        else               { in = Wo; out = Wot; base = (size_t)(b - 10240) * 1024 + t; }
        float4 v[4];
#pragma unroll
        for (int u = 0; u < 4; u++) v[u] = in[base + u * 256];
#pragma unroll
        for (int u = 0; u < 4; u++) out[base + u * 256] = round4(v[u]);
    } else {
        const float4* in = (b < 9216) ? Wk : Wv;
        const int off = (b < 9216) ? 0 : 256;
        const size_t base = (size_t)((b - 8192) & 1023) * 1024 + t;
        float4 v[4];
#pragma unroll
        for (int u = 0; u < 4; u++) v[u] = in[base + u * 256];
#pragma unroll
        for (int u = 0; u < 4; u++) {
            size_t i = base + u * 256;
            size_t row = i >> 8;
            size_t col = i & 255;
            Wkvt[row * 512 + off + col] = round4(v[u]);
        }
    }
}

// ================= tf32 mma GEMM core (BK=32, 2-stage, 4 warps x 64x64) =================
// Epilogue modes: 0 = plain fp32 write, 1 = RoPE(+tf32 round), 2 = tf32 round.
#define ASTR 36
#define BSTR 136
#define STG_A (128 * ASTR)
#define STG_B (32 * BSTR)
#define STG_FLOATS (STG_A + STG_B)           // 8960
#define GEMM_SMEM_BYTES (2 * STG_FLOATS * 4) // 71680
#define EPI_STR 130                          // epilogue staging stride (128*130*4=66560 <= 71680)

__device__ __forceinline__ void gemm_body(const float* __restrict__ Ap,
                                          const float* __restrict__ Bp,
                                          float* __restrict__ C,
                                          size_t bm, size_t bn,
                                          int N, int K, int mode,
                                          float* smg, uint32_t smb) {
    const int tid = threadIdx.x;
    const int wid = tid >> 5;
    const int lid = tid & 31;
    const int gi = lid >> 2;
    const int qi = lid & 3;
    const int wm = (wid & 1) * 64;
    const int wn = (wid >> 1) * 64;

    const int aRow = tid >> 3;
    const int aCol = (tid & 7) * 4;
    const int bRow = tid >> 5;
    const int bCol = (tid & 31) * 4;

    float acc[4][8][4];
#pragma unroll
    for (int mt = 0; mt < 4; mt++)
#pragma unroll
        for (int nt = 0; nt < 8; nt++)
#pragma unroll
            for (int r = 0; r < 4; r++) acc[mt][nt][r] = 0.0f;

    auto load_stage = [&](int kstep, int slot) {
        uint32_t as = smb + (uint32_t)(slot * STG_FLOATS) * 4u;
        uint32_t bs = as + STG_A * 4u;
        const int k0 = kstep * 32;
#pragma unroll
        for (int r = 0; r < 8; r++) {
            int row = aRow + r * 16;
            cp16(as + (row * ASTR + aCol) * 4, Ap + (size_t)row * K + k0 + aCol);
        }
#pragma unroll
        for (int r = 0; r < 8; r++) {
            int row = bRow + r * 4;
            cp16(bs + (row * BSTR + bCol) * 4, Bp + (size_t)(k0 + row) * N + bCol);
        }
    };

    const int nsteps = K / 32;
    load_stage(0, 0);
    CP_COMMIT();

    for (int step = 0; step < nsteps; step++) {
        CP_WAIT(0);
        __syncthreads();
        if (step + 1 < nsteps)
            load_stage(step + 1, (step + 1) & 1);
        CP_COMMIT();

        const float* Ab = smg + (step & 1) * STG_FLOATS;
        const float* Bb = Ab + STG_A;
#pragma unroll
        for (int kk = 0; kk < 32; kk += 8) {
            uint32_t a[4][4], b[8][2];
#pragma unroll
            for (int mt = 0; mt < 4; mt++) {
                int r = wm + mt * 16 + gi;
                a[mt][0] = __float_as_uint(Ab[r * ASTR + kk + qi]);
                a[mt][1] = __float_as_uint(Ab[(r + 8) * ASTR + kk + qi]);
                a[mt][2] = __float_as_uint(Ab[r * ASTR + kk + qi + 4]);
                a[mt][3] = __float_as_uint(Ab[(r + 8) * ASTR + kk + qi + 4]);
            }
#pragma unroll
            for (int nt = 0; nt < 8; nt++) {
                int c = wn + nt * 8 + gi;
                b[nt][0] = __float_as_uint(Bb[(kk + qi) * BSTR + c]);
                b[nt][1] = __float_as_uint(Bb[(kk + qi + 4) * BSTR + c]);
            }
#pragma unroll
            for (int mt = 0; mt < 4; mt++)
#pragma unroll
                for (int nt = 0; nt < 8; nt++)
                    mma_tf32(acc[mt][nt], a[mt][0], a[mt][1], a[mt][2], a[mt][3],
                             b[nt][0], b[nt][1]);
        }
    }

    if (mode != 1) {
#pragma unroll
        for (int mt = 0; mt < 4; mt++) {
#pragma unroll
            for (int nt = 0; nt < 8; nt++) {
                size_t row = bm + wm + mt * 16 + gi;
                size_t col = bn + wn + nt * 8 + qi * 2;
                float v0 = acc[mt][nt][0], v1 = acc[mt][nt][1];
                float v2 = acc[mt][nt][2], v3 = acc[mt][nt][3];
                if (mode == 2) {
                    v0 = __uint_as_float(f2tf32(v0));
                    v1 = __uint_as_float(f2tf32(v1));
                    v2 = __uint_as_float(f2tf32(v2));
                    v3 = __uint_as_float(f2tf32(v3));
                }
                *(float2*)&C[row * N + col] = make_float2(v0, v1);
                *(float2*)&C[(row + 8) * N + col] = make_float2(v2, v3);
            }
        }
        return;
    }

    // mode 1: RoPE epilogue. Stage tile in smem, rotate pairs (d, d+64), round, store.
    __syncthreads();  // mainloop smem reads done before overwrite
#pragma unroll
    for (int mt = 0; mt < 4; mt++) {
#pragma unroll
        for (int nt = 0; nt < 8; nt++) {
            int row = wm + mt * 16 + gi;
            int col = wn + nt * 8 + qi * 2;
            *(float2*)&smg[row * EPI_STR + col] = make_float2(acc[mt][nt][0], acc[mt][nt][1]);
            *(float2*)&smg[(row + 8) * EPI_STR + col] = make_float2(acc[mt][nt][2], acc[mt][nt][3]);
        }
    }
    __syncthreads();
    // 128 rows x 64 pairs; 128 threads -> 64 iterations
    for (int i = tid; i < 128 * 64; i += 128) {
        int row = i >> 6;
        int d = i & 63;
        int s = (int)((bm + row) & (SEQ - 1));
        float inv = exp2f(-0.20762050593046938f * (float)d);
        float ang = (float)s * inv;
        float sn, cs;
        sincosf(ang, &sn, &cs);
        float x1 = smg[row * EPI_STR + d];
        float x2 = smg[row * EPI_STR + d + 64];
        size_t grow = (bm + row) * (size_t)N + bn;
        C[grow + d]      = __uint_as_float(f2tf32(x1 * cs - x2 * sn));
        C[grow + d + 64] = __uint_as_float(f2tf32(x2 * cs + x1 * sn));
    }
}

// Merged Q + KV projection (rope fused for Q and K halves, round for V half)
__global__ __launch_bounds__(128)
void tf32_qkv_gemm(const float* __restrict__ A,
                   const float* __restrict__ Wq, const float* __restrict__ Wkv,
                   float* __restrict__ Q, float* __restrict__ KV) {
    extern __shared__ float smg[];
    const uint32_t smb = smem_u32(smg);
    const size_t bm = (size_t)blockIdx.y * 128;
    const size_t bnv = (size_t)blockIdx.x * 128;
    if (bnv < HID) {
        gemm_body(A + bm * HID, Wq + bnv, Q, bm, bnv, HID, HID, 1, smg, smb);
    } else {
        size_t bn = bnv - HID;
        int mode = (bn < KVD) ? 1 : 2;   // K half: rope; V half: round
        gemm_body(A + bm * HID, Wkv + bn, KV, bm, bn, KVSTR, HID, mode, smg, smb);
    }
}

__global__ __launch_bounds__(128)
void tf32_mma_gemm(const float* __restrict__ A, const float* __restrict__ B,
                   float* __restrict__ C, int M, int N, int K, int mode) {
    extern __shared__ float smg[];
    const uint32_t smb = smem_u32(smg);
    const size_t bm = (size_t)blockIdx.y * 128;
    const size_t bn = (size_t)blockIdx.x * 128;
    gemm_body(A + bm * K, B + bn, C, bm, bn, N, K, mode, smg, smb);
}

// ================= Flash attention (tf32 mma, causal, GQA) =================
// BQ=64, BC=32, 128 threads, 2 CTAs/SM; split K/V commit groups (R14 form).
#define QSTR 132
#define KSTR 132
#define VSTR 136
#define SQ_OFF 0
#define SK0_OFF (64 * QSTR)
#define SK1_OFF (SK0_OFF + 32 * KSTR)
#define SV0_OFF (SK1_OFF + 32 * KSTR)
#define SV1_OFF (SV0_OFF + 32 * VSTR)
#define FSM_FLOATS (SV1_OFF + 32 * VSTR)     // 25600
#define FSM_BYTES (FSM_FLOATS * 4)           // 102400

__global__ __launch_bounds__(128)
void flash_mma_kernel(const float* __restrict__ Q, const float* __restrict__ KV,
                      float* __restrict__ O) {
    extern __shared__ float sm[];
    const int tid = threadIdx.x;
    const int wid = tid >> 5;
    const int lid = tid & 31;
    const int gi = lid >> 2;
    const int qi = lid & 3;
    const int wm = wid * 16;

    const int qt = blockIdx.x;
    const int h  = blockIdx.y;
    const int b  = blockIdx.z;
    const int kvh = h >> 2;
    const int q0 = qt * 64;

    const float* Qp = Q + (size_t)b * SEQ * HID + (size_t)h * HD;
    const float* Kp = KV + (size_t)b * SEQ * KVSTR + (size_t)kvh * HD;
    const float* Vp = Kp + KVD;
    float* Op = O + (size_t)b * SEQ * HID + (size_t)h * HD;

    const uint32_t smb = smem_u32(sm);

    for (int i = tid; i < 64 * 32; i += 128) {
        int row = i >> 5, c4 = (i & 31) * 4;
        *(float4*)&sm[SQ_OFF + row * QSTR + c4] =
            *(const float4*)&Qp[(size_t)(q0 + row) * HID + c4];
    }

    float m0 = -1e30f, m1 = -1e30f, l0 = 0.0f, l1 = 0.0f;
    float o[16][4];
#pragma unroll
    for (int f = 0; f < 16; f++)
#pragma unroll
        for (int r = 0; r < 4; r++) o[f][r] = 0.0f;

    const int ntiles = 2 * qt + 2;
    const float qscale = 0.08838834764831845f;

    auto load_k = [&](int j, int slot) {
        uint32_t kb = smb + (slot ? SK1_OFF : SK0_OFF) * 4;
        const size_t r0 = (size_t)j * 32;
        for (int i = tid; i < 32 * 32; i += 128) {
            int row = i >> 5, c4 = (i & 31) * 4;
            cp16(kb + (row * KSTR + c4) * 4, Kp + (r0 + row) * KVSTR + c4);
        }
    };
    auto load_v = [&](int j, int slot) {
        uint32_t vb = smb + (slot ? SV1_OFF : SV0_OFF) * 4;
        const size_t r0 = (size_t)j * 32;
        for (int i = tid; i < 32 * 32; i += 128) {
            int row = i >> 5, c4 = (i & 31) * 4;
            cp16(vb + (row * VSTR + c4) * 4, Vp + (r0 + row) * KVSTR + c4);
        }
    };

    load_k(0, 0);
    CP_COMMIT();
    load_v(0, 0);
    CP_COMMIT();

    for (int j = 0; j < ntiles; j++) {
        const int cur = j & 1;
        CP_WAIT(1);
        __syncthreads();

        if (j + 1 < ntiles) {
            load_k(j + 1, (j + 1) & 1);
        }
        CP_COMMIT();

        const float* sK = sm + (cur ? SK1_OFF : SK0_OFF);
        const float* sV = sm + (cur ? SV1_OFF : SV0_OFF);
        const float* sQ = sm + SQ_OFF;

        float s[4][4];
#pragma unroll
        for (int nt = 0; nt < 4; nt++)
#pragma unroll
            for (int r = 0; r < 4; r++) s[nt][r] = 0.0f;

#pragma unroll
        for (int kk = 0; kk < 128; kk += 8) {
            uint32_t a0 = __float_as_uint(sQ[(wm + gi) * QSTR + kk + qi]);
            uint32_t a1 = __float_as_uint(sQ[(wm + gi + 8) * QSTR + kk + qi]);
            uint32_t a2 = __float_as_uint(sQ[(wm + gi) * QSTR + kk + qi + 4]);
            uint32_t a3 = __float_as_uint(sQ[(wm + gi + 8) * QSTR + kk + qi + 4]);
#pragma unroll
            for (int nt = 0; nt < 4; nt++) {
                uint32_t b0 = __float_as_uint(sK[(nt * 8 + gi) * KSTR + kk + qi]);
                uint32_t b1 = __float_as_uint(sK[(nt * 8 + gi) * KSTR + kk + qi + 4]);
                mma_tf32(s[nt], a0, a1, a2, a3, b0, b1);
            }
        }

        const int row0 = q0 + wm + gi;
        const int row1 = row0 + 8;
        const bool diag = (j >= 2 * qt);
#pragma unroll
        for (int nt = 0; nt < 4; nt++) {
#pragma unroll
            for (int r = 0; r < 4; r++) s[nt][r] *= qscale;
            if (diag) {
                int c = j * 32 + nt * 8 + 2 * qi;
                if (c > row0)     s[nt][0] = -1e30f;
                if (c + 1 > row0) s[nt][1] = -1e30f;
                if (c > row1)     s[nt][2] = -1e30f;
                if (c + 1 > row1) s[nt][3] = -1e30f;
            }
        }
        float mx0 = -1e30f, mx1 = -1e30f;
#pragma unroll
        for (int nt = 0; nt < 4; nt++) {
            mx0 = fmaxf(mx0, fmaxf(s[nt][0], s[nt][1]));
            mx1 = fmaxf(mx1, fmaxf(s[nt][2], s[nt][3]));
        }
        mx0 = fmaxf(mx0, __shfl_xor_sync(0xffffffffu, mx0, 1));
        mx0 = fmaxf(mx0, __shfl_xor_sync(0xffffffffu, mx0, 2));
        mx1 = fmaxf(mx1, __shfl_xor_sync(0xffffffffu, mx1, 1));
        mx1 = fmaxf(mx1, __shfl_xor_sync(0xffffffffu, mx1, 2));

        float mn0 = fmaxf(m0, mx0), mn1 = fmaxf(m1, mx1);
        float sc0 = __expf(m0 - mn0), sc1 = __expf(m1 - mn1);
        m0 = mn0; m1 = mn1;

        float rs0 = 0.0f, rs1 = 0.0f;
        uint32_t pu[4][4];
#pragma unroll
        for (int nt = 0; nt < 4; nt++) {
            float p0 = __expf(s[nt][0] - m0);
            float p1 = __expf(s[nt][1] - m0);
            float p2 = __expf(s[nt][2] - m1);
            float p3 = __expf(s[nt][3] - m1);
            rs0 += p0 + p1;
            rs1 += p2 + p3;
            pu[nt][0] = f2tf32(p0);
            pu[nt][1] = f2tf32(p1);
            pu[nt][2] = f2tf32(p2);
            pu[nt][3] = f2tf32(p3);
        }
        rs0 += __shfl_xor_sync(0xffffffffu, rs0, 1);
        rs0 += __shfl_xor_sync(0xffffffffu, rs0, 2);
        rs1 += __shfl_xor_sync(0xffffffffu, rs1, 1);
        rs1 += __shfl_xor_sync(0xffffffffu, rs1, 2);
        l0 = l0 * sc0 + rs0;
        l1 = l1 * sc1 + rs1;
#pragma unroll
        for (int f = 0; f < 16; f++) {
            o[f][0] *= sc0; o[f][1] *= sc0;
            o[f][2] *= sc1; o[f][3] *= sc1;
        }

        CP_WAIT(1);
        __syncthreads();

        if (j + 1 < ntiles) {
            load_v(j + 1, (j + 1) & 1);
        }
        CP_COMMIT();

        const int srcA = (gi << 2) + (qi >> 1);
        const int srcB = srcA + 2;
        const bool odd = (qi & 1);
#pragma unroll
        for (int kc = 0; kc < 4; kc++) {
            uint32_t x0 = __shfl_sync(0xffffffffu, pu[kc][0], srcA);
            uint32_t x1 = __shfl_sync(0xffffffffu, pu[kc][1], srcA);
            uint32_t y0 = __shfl_sync(0xffffffffu, pu[kc][0], srcB);
            uint32_t y1 = __shfl_sync(0xffffffffu, pu[kc][1], srcB);
            uint32_t x2 = __shfl_sync(0xffffffffu, pu[kc][2], srcA);
            uint32_t x3 = __shfl_sync(0xffffffffu, pu[kc][3], srcA);
            uint32_t y2 = __shfl_sync(0xffffffffu, pu[kc][2], srcB);
            uint32_t y3 = __shfl_sync(0xffffffffu, pu[kc][3], srcB);
            uint32_t a0 = odd ? x1 : x0;
            uint32_t a2 = odd ? y1 : y0;
            uint32_t a1 = odd ? x3 : x2;
            uint32_t a3 = odd ? y3 : y2;
#pragma unroll
            for (int nt2 = 0; nt2 < 16; nt2++) {
                uint32_t b0 = __float_as_uint(sV[(kc * 8 + qi) * VSTR + nt2 * 8 + gi]);
                uint32_t b1 = __float_as_uint(sV[(kc * 8 + qi + 4) * VSTR + nt2 * 8 + gi]);
                mma_tf32(o[nt2], a0, a1, a2, a3, b0, b1);
            }
        }
    }

    const float inv0 = 1.0f / l0;
    const float inv1 = 1.0f / l1;
    const size_t r0 = (size_t)(q0 + wm + gi);
    const size_t r1 = r0 + 8;
#pragma unroll
    for (int nt2 = 0; nt2 < 16; nt2++) {
        int col = nt2 * 8 + 2 * qi;
        *(float2*)&Op[r0 * HID + col] = make_float2(
            __uint_as_float(f2tf32(o[nt2][0] * inv0)),
            __uint_as_float(f2tf32(o[nt2][1] * inv0)));
        *(float2*)&Op[r1 * HID + col] = make_float2(
            __uint_as_float(f2tf32(o[nt2][2] * inv1)),
            __uint_as_float(f2tf32(o[nt2][3] * inv1)));
    }
}

// ---------------- launch ----------------
extern "C" void kernel_launch(void* const* d_in, const int* in_sizes, int n_in,
                              void* d_out, int out_size) {
    (void)in_sizes; (void)n_in; (void)out_size;
    const float* X  = (const float*)d_in[0];
    const float* Wq = (const float*)d_in[3];
    const float* Wk = (const float*)d_in[4];
    const float* Wv = (const float*)d_in[5];
    const float* Wo = (const float*)d_in[6];
    float* out = (float*)d_out;

    float *Qb, *KVb, *Ob, *Xt, *Wqt, *Wkvt, *Wot;
    cudaGetSymbolAddress((void**)&Qb, g_Q);
    cudaGetSymbolAddress((void**)&KVb, g_KV);
    cudaGetSymbolAddress((void**)&Ob, g_O);
    cudaGetSymbolAddress((void**)&Xt, g_Xt);
    cudaGetSymbolAddress((void**)&Wqt, g_Wqt);
    cudaGetSymbolAddress((void**)&Wkvt, g_Wkvt);
    cudaGetSymbolAddress((void**)&Wot, g_Wot);

    cudaFuncSetAttribute(flash_mma_kernel, cudaFuncAttributeMaxDynamicSharedMemorySize, FSM_BYTES);
    cudaFuncSetAttribute(tf32_mma_gemm, cudaFuncAttributeMaxDynamicSharedMemorySize, GEMM_SMEM_BYTES);
    cudaFuncSetAttribute(tf32_qkv_gemm, cudaFuncAttributeMaxDynamicSharedMemorySize, GEMM_SMEM_BYTES);

    // launch 0: fused tf32 rounding/packing (X, Wq, Wk|Wv, Wo)
    cvt_all_kernel<<<CVT_ALL_BLOCKS, 256>>>((const float4*)X, (float4*)Xt,
                                            (const float4*)Wq, (float4*)Wqt,
                                            (const float4*)Wk, (const float4*)Wv,
                                            (float4*)Wkvt,
                                            (const float4*)Wo, (float4*)Wot);

    // launch 1: merged Q + KV projection with fused RoPE/rounding epilogues
    tf32_qkv_gemm<<<dim3((HID + KVSTR) / 128, ROWS / 128), 128, GEMM_SMEM_BYTES>>>(
        Xt, Wqt, Wkvt, Qb, KVb);

    // launch 2: flash attention (R14 form: split K/V commit groups)
    flash_mma_kernel<<<dim3(SEQ / 64, NH, BSZ), 128, FSM_BYTES>>>(Qb, KVb, Ob);

    // launch 3: output projection (plain epilogue)
    tf32_mma_gemm<<<dim3(HID / 128, ROWS / 128), 128, GEMM_SMEM_BYTES>>>(
        Ob, Wot, out, ROWS, HID, HID, 0);
}